// round 12
// baseline (speedup 1.0000x reference)
#include <cuda_runtime.h>
#include <math.h>

#define BB 64
#define SS 512
#define HH 768
#define NT 36
#define TSTART 34
#define TSTOP 35
#define SCAN_BLOCKS 64     // one block per batch: NLL (thr 0-63) + Viterbi (thr 64-127)
#define GEMM_BLOCKS 256    // 128 rows per block, col-split: 9 warps x 4 cols
#define CHUNK 128          // rows per readiness chunk (4 per batch)
#define KT 32              // k-tile

// Scratch (device globals — no allocation allowed)
__device__ float g_emit [BB * SS * NT];
__device__ float g_eemit[BB * SS * NT];
__device__ float g_lossb[BB];
__device__ int   g_done [BB * 4];
__device__ int   g_nllcnt;

// ---------------- f32x2 helpers ----------------
__device__ __forceinline__ unsigned long long pack2(float a, float b) {
    unsigned long long r;
    asm("mov.b64 %0, {%1, %2};" : "=l"(r) : "f"(a), "f"(b));
    return r;
}
__device__ __forceinline__ void unpack2(unsigned long long v, float& a, float& b) {
    asm("mov.b64 {%0, %1}, %2;" : "=f"(a), "=f"(b) : "l"(v));
}
__device__ __forceinline__ unsigned long long fma2(unsigned long long a,
                                                   unsigned long long b,
                                                   unsigned long long c) {
    unsigned long long d;
    asm("fma.rn.f32x2 %0, %1, %2, %3;" : "=l"(d) : "l"(a), "l"(b), "l"(c));
    return d;
}
__device__ __forceinline__ unsigned long long add2(unsigned long long a,
                                                   unsigned long long b) {
    unsigned long long d;
    asm("add.rn.f32x2 %0, %1, %2;" : "=l"(d) : "l"(a), "l"(b));
    return d;
}
__device__ __forceinline__ void nbar(int id) {
    asm volatile("bar.sync %0, 64;" :: "r"(id) : "memory");
}
__device__ __forceinline__ void wait_flag(int idx) {
    volatile int* f = &g_done[idx];
    while (*f == 0) __nanosleep(64);
}

// ---------------- init ----------------
__global__ void init_kernel() {
    int i = threadIdx.x + blockIdx.x * blockDim.x;
    if (i < BB * 4) g_done[i] = 0;
    if (i == 0) g_nllcnt = 0;
}

union SmemU {
    float Xs[KT][129];             // 16512 B  k-major X tile, conflict-free
    struct {                       // 23580 B  scan state (NLL + Viterbi coexist)
        float Tsh[NT * NT];
        unsigned char bp[(SS - 1) * NT];
    } s;
};

// ---------------- fused kernel ----------------
// blocks [0,64):    combined scan for batch bid: NLL thr 0-63 (bar 1),
//                   Viterbi thr 64-127 (bar 2); thr 128+ exit
// blocks [64,320):  col-split GEMM, chunk-major: c=(bid-64)>>6, b=(bid-64)&63
// block  320:       loss reducer
__global__ __launch_bounds__(288, 3) void fused_kernel(
    const float* __restrict__ x1, const int* __restrict__ hidx,
    const float* __restrict__ W, const float* __restrict__ bias,
    const int* __restrict__ tags, const float* __restrict__ trans,
    float* __restrict__ out)
{
    __shared__ __align__(16) SmemU u;
    __shared__ int   src[128];
    __shared__ __align__(16) float bufN[2][NT];
    __shared__ __align__(16) float bufV[2][NT];
    __shared__ float redN[64], redV[64];
    __shared__ int   iredN[64], iredV[64];
    __shared__ int   sh_xlenN, sh_xlenV, sh_lastV;

    const int tid = threadIdx.x;
    const int bid = blockIdx.x;

    if (bid >= SCAN_BLOCKS && bid < SCAN_BLOCKS + GEMM_BLOCKS) {
        // ================= GEMM (col-split, full-K per thread) =================
        const int gb = bid - SCAN_BLOCKS;
        const int c  = gb >> 6;          // chunk 0..3
        const int b  = gb & 63;          // batch
        const int rowbase = b * SS + c * CHUNK;
        const int warp = tid >> 5;       // 0..8 -> cols 4*warp..4*warp+3
        const int lane = tid & 31;
        const int cw   = warp * 4;

        if (tid < 128) {
            int g = rowbase + tid;
            src[tid] = (b << 9) * HH + hidx[g] * HH;
        }

        unsigned long long acc[4][2];
#pragma unroll
        for (int r4 = 0; r4 < 4; r4++) { acc[r4][0] = 0ull; acc[r4][1] = 0ull; }

        __syncthreads();

        for (int kt = 0; kt < HH / KT; kt++) {
            const int k0 = kt * KT;
            // stage 128 rows x 32 k (threads 0-255; 8 lanes cover one row's 128B line)
            if (tid < 256) {
#pragma unroll
                for (int it = 0; it < 4; it++) {
                    int idx = tid + it * 256;       // 0..1023 float4s
                    int rr = idx >> 3, c8 = idx & 7;
                    float4 v = __ldcg(
                        reinterpret_cast<const float4*>(x1 + src[rr] + k0) + c8);
                    u.Xs[c8 * 4 + 0][rr] = v.x;
                    u.Xs[c8 * 4 + 1][rr] = v.y;
                    u.Xs[c8 * 4 + 2][rr] = v.z;
                    u.Xs[c8 * 4 + 3][rr] = v.w;
                }
            }
            __syncthreads();

#pragma unroll 8
            for (int kk = 0; kk < KT; kk++) {
                ulonglong2 wv = __ldg(reinterpret_cast<const ulonglong2*>(
                    W + (k0 + kk) * 36 + cw));      // uniform LDG.128, L1-hit
#pragma unroll
                for (int r4 = 0; r4 < 4; r4++) {
                    float x = u.Xs[kk][lane + 32 * r4];
                    unsigned long long px = pack2(x, x);
                    acc[r4][0] = fma2(px, wv.x, acc[r4][0]);
                    acc[r4][1] = fma2(px, wv.y, acc[r4][1]);
                }
            }
            __syncthreads();
        }

        // epilogue: bias + leaky + exp, direct store (no partial combine)
        const float b0 = bias[cw], b1 = bias[cw + 1], b2 = bias[cw + 2], b3 = bias[cw + 3];
#pragma unroll
        for (int r4 = 0; r4 < 4; r4++) {
            const int row = lane + 32 * r4;
            const long long grow = rowbase + row;
            float v0, v1, v2, v3;
            unpack2(acc[r4][0], v0, v1);
            unpack2(acc[r4][1], v2, v3);
            v0 += b0; v1 += b1; v2 += b2; v3 += b3;
            v0 = (v0 >= 0.f) ? v0 : 0.01f * v0;
            v1 = (v1 >= 0.f) ? v1 : 0.01f * v1;
            v2 = (v2 >= 0.f) ? v2 : 0.01f * v2;
            v3 = (v3 >= 0.f) ? v3 : 0.01f * v3;
            *reinterpret_cast<float4*>(g_emit + grow * 36 + cw) =
                make_float4(v0, v1, v2, v3);
            *reinterpret_cast<float4*>(g_eemit + grow * 36 + cw) =
                make_float4(__expf(v0), __expf(v1), __expf(v2), __expf(v3));
        }
        __syncthreads();
        if (tid == 0) {
            __threadfence();
            atomicExch(&g_done[b * 4 + c], 1);
        }
        return;
    }

    if (bid >= SCAN_BLOCKS + GEMM_BLOCKS) {
        // ================= loss reducer =================
        if (tid == 0) {
            volatile int* c = &g_nllcnt;
            while (*c < BB) __nanosleep(256);
            __threadfence();
            float a = 0.f;
            for (int i = 0; i < BB; i++) a += g_lossb[i];
            out[0] = a;
        }
        return;
    }

    // ================= SCANS =================
    const int b = bid;

    if (tid < 64) {
        // ---------------- NLL (threads 0-63, named barrier 1) ----------------
        const int j = tid;
        {
            int lm = 0;
            for (int s = tid; s < SS; s += 64) lm = max(lm, hidx[b * SS + s]);
            iredN[tid] = lm;
            nbar(1);
            if (tid == 0) {
                int m = 0;
                for (int i = 0; i < 64; i++) m = max(m, iredN[i]);
                sh_xlenN = m;
            }
            nbar(1);
        }
        const int xlen = sh_xlenN;
        const int cmax = (xlen - 1) >> 7;
        int sready = 0;

        float* Tsh = u.s.Tsh;
        for (int i = tid; i < NT * NT; i += 64) Tsh[i] = trans[i];
        nbar(1);

        unsigned long long Ecol2[18];
        float Cl = 0.f;
        if (j < NT) {
#pragma unroll
            for (int p = 0; p < 18; p++)
                Ecol2[p] = pack2(__expf(Tsh[(2 * p) * NT + j]),
                                 __expf(Tsh[(2 * p + 1) * NT + j]));
        }

        if (tid == 0) { wait_flag(b * 4 + 0); sready = 1; __threadfence(); }
        nbar(1);

        if (j < NT)
            bufN[0][j] = __expf(g_emit[(b * SS) * NT + j] + Tsh[TSTART * NT + j]);
        nbar(1);

        const float* ee = g_eemit + (long long)b * SS * NT;
        float eenext = (xlen > 1 && j < NT) ? ee[NT + j] : 0.f;
        int t = 1;
        for (int c = 0; c <= cmax; c++) {
            const int wc = min(c + 1, cmax);
            if (tid == 0) {
                for (; sready <= wc; sready++) wait_flag(b * 4 + sready);
                __threadfence();
            }
            nbar(1);
            const int tend = min((c + 1) * CHUNK, xlen);
            for (; t < tend; t++) {
                const int cur = t & 1, prev = cur ^ 1;
                float eecur = eenext;
                if (t + 1 < xlen && j < NT) eenext = ee[(t + 1) * NT + j];
                if (j < NT) {
                    const unsigned long long* vp =
                        reinterpret_cast<const unsigned long long*>(&bufN[prev][0]);
                    unsigned long long c0 = 0, c1 = 0, c2 = 0, c3 = 0;
                    float m0 = 0.f, m1 = 0.f, m2 = 0.f, m3 = 0.f;
#pragma unroll
                    for (int p = 0; p < 16; p += 4) {
                        unsigned long long v0 = vp[p], v1 = vp[p+1], v2 = vp[p+2], v3 = vp[p+3];
                        c0 = fma2(v0, Ecol2[p],   c0);
                        c1 = fma2(v1, Ecol2[p+1], c1);
                        c2 = fma2(v2, Ecol2[p+2], c2);
                        c3 = fma2(v3, Ecol2[p+3], c3);
                        float a, bb2;
                        unpack2(v0, a, bb2); m0 = fmaxf(m0, fmaxf(a, bb2));
                        unpack2(v1, a, bb2); m1 = fmaxf(m1, fmaxf(a, bb2));
                        unpack2(v2, a, bb2); m2 = fmaxf(m2, fmaxf(a, bb2));
                        unpack2(v3, a, bb2); m3 = fmaxf(m3, fmaxf(a, bb2));
                    }
                    {
                        unsigned long long v0 = vp[16], v1 = vp[17];
                        c0 = fma2(v0, Ecol2[16], c0);
                        c1 = fma2(v1, Ecol2[17], c1);
                        float a, bb2;
                        unpack2(v0, a, bb2); m0 = fmaxf(m0, fmaxf(a, bb2));
                        unpack2(v1, a, bb2); m1 = fmaxf(m1, fmaxf(a, bb2));
                    }
                    unsigned long long cs = add2(add2(c0, c1), add2(c2, c3));
                    float sa, sbv; unpack2(cs, sa, sbv);
                    float accv = sa + sbv;
                    float m = fmaxf(fmaxf(m0, m1), fmaxf(m2, m3));
                    bufN[cur][j] = accv * (1.0f / m) * eecur;
                    Cl += __logf(m);
                }
                nbar(1);
            }
        }
        const int lastbuf = (xlen >= 2) ? ((xlen - 1) & 1) : 0;
        if (j < NT) redN[j] = bufN[lastbuf][j] * __expf(Tsh[j * NT + TSTOP]);
        nbar(1);

        float logZ = 0.f;
        if (tid == 0) {
            float sZ = 0.f;
            for (int i = 0; i < NT; i++) sZ += redN[i];
            logZ = Cl + __logf(sZ);
        }
        nbar(1);

        const int* tg = tags + b * SS;
        {
            float gp = 0.f;
            for (int s = tid; s < xlen; s += 64) {
                int cs = tg[s];
                gp += g_emit[((long long)b * SS + s) * NT + cs];
                if (s >= 1) gp += Tsh[tg[s - 1] * NT + cs];
            }
            redN[tid] = gp;
        }
        nbar(1);
        if (tid == 0) {
            float g = 0.f;
            for (int i = 0; i < 64; i++) g += redN[i];
            int li = (xlen > 0) ? (xlen - 1) : 0;
            g += Tsh[TSTART * NT + tg[0]] + Tsh[tg[li] * NT + TSTOP];
            g_lossb[b] = logZ - g;
            __threadfence();
            atomicAdd(&g_nllcnt, 1);
        }
        return;
    }

    if (tid < 128) {
        // ---------------- Viterbi (threads 64-127, named barrier 2) ----------------
        const int lt = tid - 64;
        const int j = lt;
        {
            int lm = 0;
            for (int s = lt; s < SS; s += 64) lm = max(lm, hidx[b * SS + s]);
            iredV[lt] = lm;
            nbar(2);
            if (lt == 0) {
                int m = 0;
                for (int i = 0; i < 64; i++) m = max(m, iredV[i]);
                sh_xlenV = m;
            }
            nbar(2);
        }
        const int xlen = sh_xlenV;
        const int cmax = (xlen - 1) >> 7;
        int sready = 0;

        unsigned char* bp = u.s.bp;
        float Tcol[NT];
        float TjS = 0.f;
        if (j < NT) {
#pragma unroll
            for (int i = 0; i < NT; i++) Tcol[i] = trans[i * NT + j];
            TjS = trans[j * NT + TSTOP];
        }

        if (lt == 0) { wait_flag(b * 4 + 0); sready = 1; __threadfence(); }
        nbar(2);

        if (j < NT)
            bufV[0][j] = g_emit[(b * SS) * NT + j] + trans[TSTART * NT + j];
        nbar(2);

        const float* em = g_emit + (long long)b * SS * NT;
        float emnext = (xlen > 1 && j < NT) ? em[NT + j] : 0.f;
        int t = 1;
        for (int c = 0; c <= cmax; c++) {
            const int wc = min(c + 1, cmax);
            if (lt == 0) {
                for (; sready <= wc; sready++) wait_flag(b * 4 + sready);
                __threadfence();
            }
            nbar(2);
            const int tend = min((c + 1) * CHUNK, xlen);
            for (; t < tend; t++) {
                const int cur = t & 1, prev = cur ^ 1;
                float ec = emnext;
                if (t + 1 < xlen && j < NT) emnext = em[(t + 1) * NT + j];
                if (j < NT) {
                    float bb4[4] = {-1e30f, -1e30f, -1e30f, -1e30f};
                    int   bi4[4] = {0, 9, 18, 27};
#pragma unroll
                    for (int c4 = 0; c4 < 4; c4++) {
#pragma unroll
                        for (int k = 0; k < 9; k++) {
                            int i = c4 * 9 + k;
                            float v = bufV[prev][i] + Tcol[i];
                            bool gt = v > bb4[c4];
                            bb4[c4] = gt ? v : bb4[c4];
                            bi4[c4] = gt ? i : bi4[c4];
                        }
                    }
                    float best = bb4[0]; int bi = bi4[0];
                    if (bb4[1] > best) { best = bb4[1]; bi = bi4[1]; }
                    if (bb4[2] > best) { best = bb4[2]; bi = bi4[2]; }
                    if (bb4[3] > best) { best = bb4[3]; bi = bi4[3]; }
                    bufV[cur][j] = best + ec;
                    bp[(t - 1) * NT + j] = (unsigned char)bi;
                }
                nbar(2);
            }
        }
        const int lastbuf = (xlen >= 2) ? ((xlen - 1) & 1) : 0;
        if (j < NT) redV[j] = bufV[lastbuf][j] + TjS;
        nbar(2);
        if (lt == 0) {
            float bs = -1e30f; int ltag = 0;
            for (int i = 0; i < NT; i++) {
                float v = redV[i];
                if (v > bs) { bs = v; ltag = i; }
            }
            out[1 + BB * SS + b] = bs;
            sh_lastV = ltag;
        }
        nbar(2);

        float* op = out + 1 + b * SS;
        for (int s = xlen + lt; s < SS; s += 64) op[s] = 0.f;
        if (lt == 0 && xlen > 0) {
            int tag = sh_lastV;
            op[xlen - 1] = (float)tag;
            for (int t2 = xlen - 1; t2 >= 1; t2--) {
                tag = bp[(t2 - 1) * NT + tag];
                op[t2 - 1] = (float)tag;
            }
        }
        return;
    }
    // threads 128-287 of scan blocks: exit
}

extern "C" void kernel_launch(void* const* d_in, const int* in_sizes, int n_in,
                              void* d_out, int out_size) {
    const float* x1    = (const float*)d_in[0];
    const int*   hidx  = (const int*)  d_in[1];
    const int*   tags  = (const int*)  d_in[2];
    const float* W     = (const float*)d_in[3];
    const float* bias  = (const float*)d_in[4];
    const float* trans = (const float*)d_in[5];
    float* out = (float*)d_out;

    init_kernel<<<1, 256>>>();
    fused_kernel<<<SCAN_BLOCKS + GEMM_BLOCKS + 1, 288>>>(
        x1, hidx, W, bias, tags, trans, out);
}

// round 14
// speedup vs baseline: 1.2072x; 1.2072x over previous
#include <cuda_runtime.h>
#include <math.h>

#define BB 64
#define SS 512
#define HH 768
#define NT 36
#define TSTART 34
#define TSTOP 35
#define SCAN_BLOCKS 128    // 64 NLL + 64 Viterbi (r9 layout)
#define GEMM_BLOCKS 256    // 128 rows per block, col-split: 9 warps x 4 cols
#define CHUNK 128          // rows per readiness chunk (4 per batch)
#define KT 16              // k-tile
#define NTILES (HH / KT)   // 48

// Scratch (device globals — no allocation allowed)
__device__ float g_emit [BB * SS * NT];
__device__ float g_eemit[BB * SS * NT];
__device__ float g_lossb[BB];
__device__ int   g_done [BB * 4];
__device__ int   g_nllcnt;

// ---------------- helpers ----------------
__device__ __forceinline__ unsigned long long pack2(float a, float b) {
    unsigned long long r;
    asm("mov.b64 %0, {%1, %2};" : "=l"(r) : "f"(a), "f"(b));
    return r;
}
__device__ __forceinline__ void unpack2(unsigned long long v, float& a, float& b) {
    asm("mov.b64 {%0, %1}, %2;" : "=f"(a), "=f"(b) : "l"(v));
}
__device__ __forceinline__ unsigned long long fma2(unsigned long long a,
                                                   unsigned long long b,
                                                   unsigned long long c) {
    unsigned long long d;
    asm("fma.rn.f32x2 %0, %1, %2, %3;" : "=l"(d) : "l"(a), "l"(b), "l"(c));
    return d;
}
__device__ __forceinline__ unsigned long long add2(unsigned long long a,
                                                   unsigned long long b) {
    unsigned long long d;
    asm("add.rn.f32x2 %0, %1, %2;" : "=l"(d) : "l"(a), "l"(b));
    return d;
}
__device__ __forceinline__ void barr64() {
    asm volatile("bar.sync 0, 64;" ::: "memory");
}
__device__ __forceinline__ void wait_flag(int idx) {
    volatile int* f = &g_done[idx];
    while (*f == 0) __nanosleep(64);
}
__device__ __forceinline__ void cp16(unsigned int smem_dst, const void* gsrc) {
    asm volatile("cp.async.cg.shared.global [%0], [%1], 16;"
                 :: "r"(smem_dst), "l"(gsrc));
}
__device__ __forceinline__ void cp_commit() {
    asm volatile("cp.async.commit_group;" ::: "memory");
}
template<int N>
__device__ __forceinline__ void cp_wait() {
    asm volatile("cp.async.wait_group %0;" :: "n"(N) : "memory");
}

// ---------------- init ----------------
__global__ void init_kernel() {
    int i = threadIdx.x + blockIdx.x * blockDim.x;
    if (i < BB * 4) g_done[i] = 0;
    if (i == 0) g_nllcnt = 0;
}

union SmemU {
    struct {                          // 25088 B GEMM tiles (double-buffered)
        float Xs[2][128][20];         // row-major X, stride 20 (80B, 16B-aligned)
        float Ws[2][KT][36];          // W tile
    } g;
    struct {                          // 23580 B scan state
        float Tsh[NT * NT];
        unsigned char bp[(SS - 1) * NT];
    } s;
};

// ---------------- fused kernel ----------------
// blocks [0,64):    NLL scan (batch bid)
// blocks [64,128):  Viterbi (batch bid-64)
// blocks [128,384): GEMM, chunk-major: c=(bid-128)>>6, b=(bid-128)&63, 128 rows
// block  384:       loss reducer
__global__ __launch_bounds__(288, 3) void fused_kernel(
    const float* __restrict__ x1, const int* __restrict__ hidx,
    const float* __restrict__ W, const float* __restrict__ bias,
    const int* __restrict__ tags, const float* __restrict__ trans,
    float* __restrict__ out)
{
    __shared__ __align__(16) SmemU u;
    __shared__ int   src[128];
    __shared__ __align__(16) float buf[2][NT];
    __shared__ float red[64];
    __shared__ int   ired[64];
    __shared__ int   sh_xlen, sh_last;

    const int tid = threadIdx.x;
    const int bid = blockIdx.x;

    if (bid >= SCAN_BLOCKS && bid < SCAN_BLOCKS + GEMM_BLOCKS) {
        // ================= GEMM (full-K col-split, cp.async pipelined) ======
        const int gb = bid - SCAN_BLOCKS;
        const int c  = gb >> 6;          // chunk 0..3
        const int b  = gb & 63;          // batch
        const int rowbase = b * SS + c * CHUNK;
        const int warp = tid >> 5;       // 0..8 -> cols 4*warp..4*warp+3
        const int lane = tid & 31;
        const int cw   = warp * 4;

        if (tid < 128) {
            int g = rowbase + tid;
            src[tid] = (b << 9) * HH + hidx[g] * HH;
        }
        __syncthreads();

        const unsigned int sX =
            (unsigned int)__cvta_generic_to_shared(&u.g.Xs[0][0][0]);
        const unsigned int sW =
            (unsigned int)__cvta_generic_to_shared(&u.g.Ws[0][0][0]);

        unsigned long long acc[4][2];
#pragma unroll
        for (int r4 = 0; r4 < 4; r4++) { acc[r4][0] = 0ull; acc[r4][1] = 0ull; }

        // stage tile kt into buffer bsel
        auto stage = [&](int kt, int bsel) {
            const int k0 = kt * KT;
            // X: 128 rows x 16 k = 512 float4 (4 lanes per row's 64B)
            for (int i = tid; i < 512; i += 288) {
                int row = i >> 2, c4 = i & 3;
                const char* gp =
                    reinterpret_cast<const char*>(x1 + src[row] + k0) + c4 * 16;
                cp16(sX + (bsel * 128 * 20 + row * 20 + c4 * 4) * 4, gp);
            }
            // W: 16 rows x 36 cols = 144 float4, contiguous
            if (tid < 144) {
                const char* gp =
                    reinterpret_cast<const char*>(W + k0 * 36) + tid * 16;
                cp16(sW + bsel * KT * 36 * 4 + tid * 16, gp);
            }
            cp_commit();
        };

        stage(0, 0);
        for (int kt = 0; kt < NTILES; kt++) {
            const int bsel = kt & 1;
            if (kt + 1 < NTILES) { stage(kt + 1, bsel ^ 1); cp_wait<1>(); }
            else                 { cp_wait<0>(); }
            __syncthreads();

            const float* Xb = &u.g.Xs[bsel][0][0];
            const float* Wb = &u.g.Ws[bsel][0][0];
#pragma unroll
            for (int g = 0; g < 4; g++) {
                float4 xv0 = *reinterpret_cast<const float4*>(Xb + (lane)      * 20 + g * 4);
                float4 xv1 = *reinterpret_cast<const float4*>(Xb + (lane + 32) * 20 + g * 4);
                float4 xv2 = *reinterpret_cast<const float4*>(Xb + (lane + 64) * 20 + g * 4);
                float4 xv3 = *reinterpret_cast<const float4*>(Xb + (lane + 96) * 20 + g * 4);
#pragma unroll
                for (int kk = 0; kk < 4; kk++) {
                    ulonglong2 wv = *reinterpret_cast<const ulonglong2*>(
                        Wb + (g * 4 + kk) * 36 + cw);    // broadcast LDS.128
                    float x0 = (kk == 0) ? xv0.x : (kk == 1) ? xv0.y : (kk == 2) ? xv0.z : xv0.w;
                    float x1v = (kk == 0) ? xv1.x : (kk == 1) ? xv1.y : (kk == 2) ? xv1.z : xv1.w;
                    float x2 = (kk == 0) ? xv2.x : (kk == 1) ? xv2.y : (kk == 2) ? xv2.z : xv2.w;
                    float x3 = (kk == 0) ? xv3.x : (kk == 1) ? xv3.y : (kk == 2) ? xv3.z : xv3.w;
                    unsigned long long p0 = pack2(x0, x0);
                    unsigned long long p1 = pack2(x1v, x1v);
                    unsigned long long p2 = pack2(x2, x2);
                    unsigned long long p3 = pack2(x3, x3);
                    acc[0][0] = fma2(p0, wv.x, acc[0][0]);
                    acc[0][1] = fma2(p0, wv.y, acc[0][1]);
                    acc[1][0] = fma2(p1, wv.x, acc[1][0]);
                    acc[1][1] = fma2(p1, wv.y, acc[1][1]);
                    acc[2][0] = fma2(p2, wv.x, acc[2][0]);
                    acc[2][1] = fma2(p2, wv.y, acc[2][1]);
                    acc[3][0] = fma2(p3, wv.x, acc[3][0]);
                    acc[3][1] = fma2(p3, wv.y, acc[3][1]);
                }
            }
            __syncthreads();
        }

        // epilogue: bias + leaky + exp, direct store
        const float b0 = bias[cw], b1 = bias[cw + 1], b2 = bias[cw + 2], b3 = bias[cw + 3];
#pragma unroll
        for (int r4 = 0; r4 < 4; r4++) {
            const int row = lane + 32 * r4;
            const long long grow = rowbase + row;
            float v0, v1, v2, v3;
            unpack2(acc[r4][0], v0, v1);
            unpack2(acc[r4][1], v2, v3);
            v0 += b0; v1 += b1; v2 += b2; v3 += b3;
            v0 = (v0 >= 0.f) ? v0 : 0.01f * v0;
            v1 = (v1 >= 0.f) ? v1 : 0.01f * v1;
            v2 = (v2 >= 0.f) ? v2 : 0.01f * v2;
            v3 = (v3 >= 0.f) ? v3 : 0.01f * v3;
            *reinterpret_cast<float4*>(g_emit + grow * 36 + cw) =
                make_float4(v0, v1, v2, v3);
            *reinterpret_cast<float4*>(g_eemit + grow * 36 + cw) =
                make_float4(__expf(v0), __expf(v1), __expf(v2), __expf(v3));
        }
        __syncthreads();
        if (tid == 0) {
            __threadfence();
            atomicExch(&g_done[b * 4 + c], 1);
        }
        return;
    }

    if (bid >= SCAN_BLOCKS + GEMM_BLOCKS) {
        // ================= loss reducer =================
        if (tid == 0) {
            volatile int* c = &g_nllcnt;
            while (*c < BB) __nanosleep(256);
            __threadfence();
            float a = 0.f;
            for (int i = 0; i < BB; i++) a += g_lossb[i];
            out[0] = a;
        }
        return;
    }

    // ================= SCANS (threads 0-63 only) =================
    if (tid >= 64) return;

    const int b = bid & 63;
    const bool viterbi = (bid >= BB);
    const int j = tid;

    // xlen = max(head_indexes[b, :])
    {
        int lm = 0;
        for (int s = tid; s < SS; s += 64) lm = max(lm, hidx[b * SS + s]);
        ired[tid] = lm;
        barr64();
        if (tid == 0) {
            int m = 0;
            for (int i = 0; i < 64; i++) m = max(m, ired[i]);
            sh_xlen = m;
        }
        barr64();
    }
    const int xlen = sh_xlen;
    const int cmax = (xlen - 1) >> 7;    // 128-row chunks
    int sready = 0;

    if (!viterbi) {
        // ---------------- NLL (scaled forward) ----------------
        float* Tsh = u.s.Tsh;
        for (int i = tid; i < NT * NT; i += 64) Tsh[i] = trans[i];
        barr64();

        unsigned long long Ecol2[18];
        float Cl = 0.f;
        if (j < NT) {
#pragma unroll
            for (int p = 0; p < 18; p++)
                Ecol2[p] = pack2(__expf(Tsh[(2 * p) * NT + j]),
                                 __expf(Tsh[(2 * p + 1) * NT + j]));
        }

        if (tid == 0) { wait_flag(b * 4 + 0); sready = 1; __threadfence(); }
        barr64();

        if (j < NT)
            buf[0][j] = __expf(g_emit[(b * SS) * NT + j] + Tsh[TSTART * NT + j]);
        barr64();

        const float* ee = g_eemit + (long long)b * SS * NT;
        float eenext = (xlen > 1 && j < NT) ? ee[NT + j] : 0.f;
        int t = 1;
        for (int c = 0; c <= cmax; c++) {
            const int wc = min(c + 1, cmax);
            if (tid == 0) {
                for (; sready <= wc; sready++) wait_flag(b * 4 + sready);
                __threadfence();
            }
            barr64();
            const int tend = min((c + 1) * CHUNK, xlen);
            for (; t < tend; t++) {
                const int cur = t & 1, prev = cur ^ 1;
                float eecur = eenext;
                if (t + 1 < xlen && j < NT) eenext = ee[(t + 1) * NT + j];
                if (j < NT) {
                    const unsigned long long* vp =
                        reinterpret_cast<const unsigned long long*>(&buf[prev][0]);
                    unsigned long long c0 = 0, c1 = 0, c2 = 0, c3 = 0;
                    float m0 = 0.f, m1 = 0.f, m2 = 0.f, m3 = 0.f;
#pragma unroll
                    for (int p = 0; p < 16; p += 4) {
                        unsigned long long v0 = vp[p], v1 = vp[p+1], v2 = vp[p+2], v3 = vp[p+3];
                        c0 = fma2(v0, Ecol2[p],   c0);
                        c1 = fma2(v1, Ecol2[p+1], c1);
                        c2 = fma2(v2, Ecol2[p+2], c2);
                        c3 = fma2(v3, Ecol2[p+3], c3);
                        float a, bb2;
                        unpack2(v0, a, bb2); m0 = fmaxf(m0, fmaxf(a, bb2));
                        unpack2(v1, a, bb2); m1 = fmaxf(m1, fmaxf(a, bb2));
                        unpack2(v2, a, bb2); m2 = fmaxf(m2, fmaxf(a, bb2));
                        unpack2(v3, a, bb2); m3 = fmaxf(m3, fmaxf(a, bb2));
                    }
                    {
                        unsigned long long v0 = vp[16], v1 = vp[17];
                        c0 = fma2(v0, Ecol2[16], c0);
                        c1 = fma2(v1, Ecol2[17], c1);
                        float a, bb2;
                        unpack2(v0, a, bb2); m0 = fmaxf(m0, fmaxf(a, bb2));
                        unpack2(v1, a, bb2); m1 = fmaxf(m1, fmaxf(a, bb2));
                    }
                    unsigned long long cs = add2(add2(c0, c1), add2(c2, c3));
                    float sa, sbv; unpack2(cs, sa, sbv);
                    float accv = sa + sbv;
                    float m = fmaxf(fmaxf(m0, m1), fmaxf(m2, m3));
                    buf[cur][j] = accv * (1.0f / m) * eecur;
                    Cl += __logf(m);
                }
                barr64();
            }
        }
        const int lastbuf = (xlen >= 2) ? ((xlen - 1) & 1) : 0;
        if (j < NT) red[j] = buf[lastbuf][j] * __expf(Tsh[j * NT + TSTOP]);
        barr64();

        float logZ = 0.f;
        if (tid == 0) {
            float sZ = 0.f;
            for (int i = 0; i < NT; i++) sZ += red[i];
            logZ = Cl + __logf(sZ);
        }
        barr64();

        const int* tg = tags + b * SS;
        {
            float gp = 0.f;
            for (int s = tid; s < xlen; s += 64) {
                int cs = tg[s];
                gp += g_emit[((long long)b * SS + s) * NT + cs];
                if (s >= 1) gp += Tsh[tg[s - 1] * NT + cs];
            }
            red[tid] = gp;
        }
        barr64();
        if (tid == 0) {
            float g = 0.f;
            for (int i = 0; i < 64; i++) g += red[i];
            int li = (xlen > 0) ? (xlen - 1) : 0;
            g += Tsh[TSTART * NT + tg[0]] + Tsh[tg[li] * NT + TSTOP];
            g_lossb[b] = logZ - g;
            __threadfence();
            atomicAdd(&g_nllcnt, 1);
        }
    } else {
        // ---------------- Viterbi ----------------
        unsigned char* bp = u.s.bp;
        float Tcol[NT];
        float TjS = 0.f;
        if (j < NT) {
#pragma unroll
            for (int i = 0; i < NT; i++) Tcol[i] = trans[i * NT + j];
            TjS = trans[j * NT + TSTOP];
        }

        if (tid == 0) { wait_flag(b * 4 + 0); sready = 1; __threadfence(); }
        barr64();

        if (j < NT)
            buf[0][j] = g_emit[(b * SS) * NT + j] + trans[TSTART * NT + j];
        barr64();

        const float* em = g_emit + (long long)b * SS * NT;
        float emnext = (xlen > 1 && j < NT) ? em[NT + j] : 0.f;
        int t = 1;
        for (int c = 0; c <= cmax; c++) {
            const int wc = min(c + 1, cmax);
            if (tid == 0) {
                for (; sready <= wc; sready++) wait_flag(b * 4 + sready);
                __threadfence();
            }
            barr64();
            const int tend = min((c + 1) * CHUNK, xlen);
            for (; t < tend; t++) {
                const int cur = t & 1, prev = cur ^ 1;
                float ec = emnext;
                if (t + 1 < xlen && j < NT) emnext = em[(t + 1) * NT + j];
                if (j < NT) {
                    float bb4[4] = {-1e30f, -1e30f, -1e30f, -1e30f};
                    int   bi4[4] = {0, 9, 18, 27};
#pragma unroll
                    for (int c4 = 0; c4 < 4; c4++) {
#pragma unroll
                        for (int k = 0; k < 9; k++) {
                            int i = c4 * 9 + k;
                            float v = buf[prev][i] + Tcol[i];
                            bool gt = v > bb4[c4];
                            bb4[c4] = gt ? v : bb4[c4];
                            bi4[c4] = gt ? i : bi4[c4];
                        }
                    }
                    float best = bb4[0]; int bi = bi4[0];
                    if (bb4[1] > best) { best = bb4[1]; bi = bi4[1]; }
                    if (bb4[2] > best) { best = bb4[2]; bi = bi4[2]; }
                    if (bb4[3] > best) { best = bb4[3]; bi = bi4[3]; }
                    buf[cur][j] = best + ec;
                    bp[(t - 1) * NT + j] = (unsigned char)bi;
                }
                barr64();
            }
        }
        const int lastbuf = (xlen >= 2) ? ((xlen - 1) & 1) : 0;
        if (j < NT) red[j] = buf[lastbuf][j] + TjS;
        barr64();
        if (tid == 0) {
            float bs = -1e30f; int lt = 0;
            for (int i = 0; i < NT; i++) {
                float v = red[i];
                if (v > bs) { bs = v; lt = i; }
            }
            out[1 + BB * SS + b] = bs;
            sh_last = lt;
        }
        barr64();

        float* op = out + 1 + b * SS;
        for (int s = xlen + tid; s < SS; s += 64) op[s] = 0.f;
        if (tid == 0 && xlen > 0) {
            int tag = sh_last;
            op[xlen - 1] = (float)tag;
            for (int t2 = xlen - 1; t2 >= 1; t2--) {
                tag = bp[(t2 - 1) * NT + tag];
                op[t2 - 1] = (float)tag;
            }
        }
    }
}

extern "C" void kernel_launch(void* const* d_in, const int* in_sizes, int n_in,
                              void* d_out, int out_size) {
    const float* x1    = (const float*)d_in[0];
    const int*   hidx  = (const int*)  d_in[1];
    const int*   tags  = (const int*)  d_in[2];
    const float* W     = (const float*)d_in[3];
    const float* bias  = (const float*)d_in[4];
    const float* trans = (const float*)d_in[5];
    float* out = (float*)d_out;

    init_kernel<<<1, 256>>>();
    fused_kernel<<<SCAN_BLOCKS + GEMM_BLOCKS + 1, 288>>>(
        x1, hidx, W, bias, tags, trans, out);
}

// round 15
// speedup vs baseline: 1.3031x; 1.0794x over previous
#include <cuda_runtime.h>
#include <math.h>

#define BB 64
#define SS 512
#define HH 768
#define NT 36
#define TSTART 34
#define TSTOP 35
#define SCAN_BLOCKS 128    // 64 NLL + 64 Viterbi
#define GEMM_BLOCKS 256    // 128 rows per block, col-split: 9 warps x 4 cols
#define CHUNK 128          // rows per readiness chunk (4 per batch)
#define KT 16              // k-tile
#define NTILES (HH / KT)   // 48

// Scratch (device globals — no allocation allowed)
__device__ float g_emit [BB * SS * NT];
__device__ float g_eemit[BB * SS * NT];
__device__ float g_lossb[BB];
__device__ int   g_done [BB * 4];
__device__ int   g_nllcnt;

// ---------------- helpers ----------------
__device__ __forceinline__ unsigned long long pack2(float a, float b) {
    unsigned long long r;
    asm("mov.b64 %0, {%1, %2};" : "=l"(r) : "f"(a), "f"(b));
    return r;
}
__device__ __forceinline__ void unpack2(unsigned long long v, float& a, float& b) {
    asm("mov.b64 {%0, %1}, %2;" : "=f"(a), "=f"(b) : "l"(v));
}
__device__ __forceinline__ unsigned long long fma2(unsigned long long a,
                                                   unsigned long long b,
                                                   unsigned long long c) {
    unsigned long long d;
    asm("fma.rn.f32x2 %0, %1, %2, %3;" : "=l"(d) : "l"(a), "l"(b), "l"(c));
    return d;
}
__device__ __forceinline__ unsigned long long add2(unsigned long long a,
                                                   unsigned long long b) {
    unsigned long long d;
    asm("add.rn.f32x2 %0, %1, %2;" : "=l"(d) : "l"(a), "l"(b));
    return d;
}
__device__ __forceinline__ void barr64() {
    asm volatile("bar.sync 0, 64;" ::: "memory");
}
__device__ __forceinline__ void barr128() {
    asm volatile("bar.sync 0, 128;" ::: "memory");
}
__device__ __forceinline__ void wait_flag(int idx) {
    volatile int* f = &g_done[idx];
    while (*f == 0) __nanosleep(64);
}
__device__ __forceinline__ void cp16(unsigned int smem_dst, const void* gsrc) {
    asm volatile("cp.async.cg.shared.global [%0], [%1], 16;"
                 :: "r"(smem_dst), "l"(gsrc));
}
__device__ __forceinline__ void cp_commit() {
    asm volatile("cp.async.commit_group;" ::: "memory");
}
template<int N>
__device__ __forceinline__ void cp_wait() {
    asm volatile("cp.async.wait_group %0;" :: "n"(N) : "memory");
}

// ---------------- init ----------------
__global__ void init_kernel() {
    int i = threadIdx.x + blockIdx.x * blockDim.x;
    if (i < BB * 4) g_done[i] = 0;
    if (i == 0) g_nllcnt = 0;
}

union SmemU {
    struct {                          // 25088 B GEMM tiles (double-buffered)
        float Xs[2][128][20];         // row-major X, stride 20 (80B, 16B-aligned)
        float Ws[2][KT][36];          // W tile
    } g;
    struct {                          // 23580 B scan state
        float Tsh[NT * NT];
        unsigned char bp[(SS - 1) * NT];
    } s;
};

// ---------------- fused kernel ----------------
// blocks [0,64):    NLL scan (batch bid), threads 0-63
// blocks [64,128):  Viterbi (batch bid-64), threads 0-127 (two-half max split)
// blocks [128,384): GEMM, chunk-major: c=(bid-128)>>6, b=(bid-128)&63, 128 rows
// block  384:       loss reducer
__global__ __launch_bounds__(288, 3) void fused_kernel(
    const float* __restrict__ x1, const int* __restrict__ hidx,
    const float* __restrict__ W, const float* __restrict__ bias,
    const int* __restrict__ tags, const float* __restrict__ trans,
    float* __restrict__ out)
{
    __shared__ __align__(16) SmemU u;
    __shared__ int   src[128];
    __shared__ __align__(16) float buf[2][NT];
    __shared__ float red[64];
    __shared__ int   ired[64];
    __shared__ float candv[2][NT];
    __shared__ int   candi[2][NT];
    __shared__ int   sh_xlen, sh_last;

    const int tid = threadIdx.x;
    const int bid = blockIdx.x;

    if (bid >= SCAN_BLOCKS && bid < SCAN_BLOCKS + GEMM_BLOCKS) {
        // ================= GEMM (full-K col-split, cp.async pipelined) ======
        const int gb = bid - SCAN_BLOCKS;
        const int c  = gb >> 6;          // chunk 0..3
        const int b  = gb & 63;          // batch
        const int rowbase = b * SS + c * CHUNK;
        const int warp = tid >> 5;       // 0..8 -> cols 4*warp..4*warp+3
        const int lane = tid & 31;
        const int cw   = warp * 4;

        if (tid < 128) {
            int g = rowbase + tid;
            src[tid] = (b << 9) * HH + hidx[g] * HH;
        }
        __syncthreads();

        const unsigned int sX =
            (unsigned int)__cvta_generic_to_shared(&u.g.Xs[0][0][0]);
        const unsigned int sW =
            (unsigned int)__cvta_generic_to_shared(&u.g.Ws[0][0][0]);

        unsigned long long acc[4][2];
#pragma unroll
        for (int r4 = 0; r4 < 4; r4++) { acc[r4][0] = 0ull; acc[r4][1] = 0ull; }

        auto stage = [&](int kt, int bsel) {
            const int k0 = kt * KT;
            for (int i = tid; i < 512; i += 288) {
                int row = i >> 2, c4 = i & 3;
                const char* gp =
                    reinterpret_cast<const char*>(x1 + src[row] + k0) + c4 * 16;
                cp16(sX + (bsel * 128 * 20 + row * 20 + c4 * 4) * 4, gp);
            }
            if (tid < 144) {
                const char* gp =
                    reinterpret_cast<const char*>(W + k0 * 36) + tid * 16;
                cp16(sW + bsel * KT * 36 * 4 + tid * 16, gp);
            }
            cp_commit();
        };

        stage(0, 0);
        for (int kt = 0; kt < NTILES; kt++) {
            const int bsel = kt & 1;
            if (kt + 1 < NTILES) { stage(kt + 1, bsel ^ 1); cp_wait<1>(); }
            else                 { cp_wait<0>(); }
            __syncthreads();

            const float* Xb = &u.g.Xs[bsel][0][0];
            const float* Wb = &u.g.Ws[bsel][0][0];
#pragma unroll
            for (int g = 0; g < 4; g++) {
                float4 xv0 = *reinterpret_cast<const float4*>(Xb + (lane)      * 20 + g * 4);
                float4 xv1 = *reinterpret_cast<const float4*>(Xb + (lane + 32) * 20 + g * 4);
                float4 xv2 = *reinterpret_cast<const float4*>(Xb + (lane + 64) * 20 + g * 4);
                float4 xv3 = *reinterpret_cast<const float4*>(Xb + (lane + 96) * 20 + g * 4);
#pragma unroll
                for (int kk = 0; kk < 4; kk++) {
                    ulonglong2 wv = *reinterpret_cast<const ulonglong2*>(
                        Wb + (g * 4 + kk) * 36 + cw);    // broadcast LDS.128
                    float x0 = (kk == 0) ? xv0.x : (kk == 1) ? xv0.y : (kk == 2) ? xv0.z : xv0.w;
                    float x1v = (kk == 0) ? xv1.x : (kk == 1) ? xv1.y : (kk == 2) ? xv1.z : xv1.w;
                    float x2 = (kk == 0) ? xv2.x : (kk == 1) ? xv2.y : (kk == 2) ? xv2.z : xv2.w;
                    float x3 = (kk == 0) ? xv3.x : (kk == 1) ? xv3.y : (kk == 2) ? xv3.z : xv3.w;
                    unsigned long long p0 = pack2(x0, x0);
                    unsigned long long p1 = pack2(x1v, x1v);
                    unsigned long long p2 = pack2(x2, x2);
                    unsigned long long p3 = pack2(x3, x3);
                    acc[0][0] = fma2(p0, wv.x, acc[0][0]);
                    acc[0][1] = fma2(p0, wv.y, acc[0][1]);
                    acc[1][0] = fma2(p1, wv.x, acc[1][0]);
                    acc[1][1] = fma2(p1, wv.y, acc[1][1]);
                    acc[2][0] = fma2(p2, wv.x, acc[2][0]);
                    acc[2][1] = fma2(p2, wv.y, acc[2][1]);
                    acc[3][0] = fma2(p3, wv.x, acc[3][0]);
                    acc[3][1] = fma2(p3, wv.y, acc[3][1]);
                }
            }
            __syncthreads();
        }

        const float b0 = bias[cw], b1 = bias[cw + 1], b2 = bias[cw + 2], b3 = bias[cw + 3];
#pragma unroll
        for (int r4 = 0; r4 < 4; r4++) {
            const int row = lane + 32 * r4;
            const long long grow = rowbase + row;
            float v0, v1, v2, v3;
            unpack2(acc[r4][0], v0, v1);
            unpack2(acc[r4][1], v2, v3);
            v0 += b0; v1 += b1; v2 += b2; v3 += b3;
            v0 = (v0 >= 0.f) ? v0 : 0.01f * v0;
            v1 = (v1 >= 0.f) ? v1 : 0.01f * v1;
            v2 = (v2 >= 0.f) ? v2 : 0.01f * v2;
            v3 = (v3 >= 0.f) ? v3 : 0.01f * v3;
            *reinterpret_cast<float4*>(g_emit + grow * 36 + cw) =
                make_float4(v0, v1, v2, v3);
            *reinterpret_cast<float4*>(g_eemit + grow * 36 + cw) =
                make_float4(__expf(v0), __expf(v1), __expf(v2), __expf(v3));
        }
        __syncthreads();
        if (tid == 0) {
            __threadfence();
            atomicExch(&g_done[b * 4 + c], 1);
        }
        return;
    }

    if (bid >= SCAN_BLOCKS + GEMM_BLOCKS) {
        // ================= loss reducer =================
        if (tid == 0) {
            volatile int* c = &g_nllcnt;
            while (*c < BB) __nanosleep(256);
            __threadfence();
            float a = 0.f;
            for (int i = 0; i < BB; i++) a += g_lossb[i];
            out[0] = a;
        }
        return;
    }

    // ================= SCANS =================
    const int b = bid & 63;
    const bool viterbi = (bid >= BB);

    if (!viterbi) {
        // ---------------- NLL (threads 0-63, cheap scalar normalizer) ------
        if (tid >= 64) return;
        const int j = tid;

        {
            int lm = 0;
            for (int s = tid; s < SS; s += 64) lm = max(lm, hidx[b * SS + s]);
            ired[tid] = lm;
            barr64();
            if (tid == 0) {
                int m = 0;
                for (int i = 0; i < 64; i++) m = max(m, ired[i]);
                sh_xlen = m;
            }
            barr64();
        }
        const int xlen = sh_xlen;
        const int cmax = (xlen - 1) >> 7;
        int sready = 0;

        float* Tsh = u.s.Tsh;
        for (int i = tid; i < NT * NT; i += 64) Tsh[i] = trans[i];
        barr64();

        unsigned long long Ecol2[18];
        float Cl = 0.f;
        if (j < NT) {
#pragma unroll
            for (int p = 0; p < 18; p++)
                Ecol2[p] = pack2(__expf(Tsh[(2 * p) * NT + j]),
                                 __expf(Tsh[(2 * p + 1) * NT + j]));
        }

        if (tid == 0) { wait_flag(b * 4 + 0); sready = 1; __threadfence(); }
        barr64();

        if (j < NT)
            buf[0][j] = __expf(g_emit[(b * SS) * NT + j] + Tsh[TSTART * NT + j]);
        barr64();

        const float* ee = g_eemit + (long long)b * SS * NT;
        float eenext = (xlen > 1 && j < NT) ? ee[NT + j] : 0.f;
        int t = 1;
        for (int c = 0; c <= cmax; c++) {
            const int wc = min(c + 1, cmax);
            if (tid == 0) {
                for (; sready <= wc; sready++) wait_flag(b * 4 + sready);
                __threadfence();
            }
            barr64();
            const int tend = min((c + 1) * CHUNK, xlen);
            for (; t < tend; t++) {
                const int cur = t & 1, prev = cur ^ 1;
                float eecur = eenext;
                if (t + 1 < xlen && j < NT) eenext = ee[(t + 1) * NT + j];
                if (j < NT) {
                    const unsigned long long* vp =
                        reinterpret_cast<const unsigned long long*>(&buf[prev][0]);
                    // normalizer: any positive scalar works; use prev state[0]
                    float nb = buf[prev][0];
                    float rinv = 1.0f / nb;
                    unsigned long long c0 = 0, c1 = 0, c2 = 0, c3 = 0;
#pragma unroll
                    for (int p = 0; p < 16; p += 4) {
                        c0 = fma2(vp[p],     Ecol2[p],     c0);
                        c1 = fma2(vp[p + 1], Ecol2[p + 1], c1);
                        c2 = fma2(vp[p + 2], Ecol2[p + 2], c2);
                        c3 = fma2(vp[p + 3], Ecol2[p + 3], c3);
                    }
                    c0 = fma2(vp[16], Ecol2[16], c0);
                    c1 = fma2(vp[17], Ecol2[17], c1);
                    unsigned long long cs = add2(add2(c0, c1), add2(c2, c3));
                    float sa, sbv; unpack2(cs, sa, sbv);
                    buf[cur][j] = (sa + sbv) * rinv * eecur;
                    Cl += __logf(nb);
                }
                barr64();
            }
        }
        const int lastbuf = (xlen >= 2) ? ((xlen - 1) & 1) : 0;
        if (j < NT) red[j] = buf[lastbuf][j] * __expf(Tsh[j * NT + TSTOP]);
        barr64();

        float logZ = 0.f;
        if (tid == 0) {
            float sZ = 0.f;
            for (int i = 0; i < NT; i++) sZ += red[i];
            logZ = Cl + __logf(sZ);
        }
        barr64();

        const int* tg = tags + b * SS;
        {
            float gp = 0.f;
            for (int s = tid; s < xlen; s += 64) {
                int cs = tg[s];
                gp += g_emit[((long long)b * SS + s) * NT + cs];
                if (s >= 1) gp += Tsh[tg[s - 1] * NT + cs];
            }
            red[tid] = gp;
        }
        barr64();
        if (tid == 0) {
            float g = 0.f;
            for (int i = 0; i < 64; i++) g += red[i];
            int li = (xlen > 0) ? (xlen - 1) : 0;
            g += Tsh[TSTART * NT + tg[0]] + Tsh[tg[li] * NT + TSTOP];
            g_lossb[b] = logZ - g;
            __threadfence();
            atomicAdd(&g_nllcnt, 1);
        }
        return;
    }

    // ---------------- Viterbi (threads 0-127, two-half max split) ----------
    if (tid >= 128) return;
    const int h = tid >> 6;          // half: i in [18h, 18h+18)
    const int j = tid & 63;          // tag (active if j < 36)

    {
        if (h == 0) {
            int lm = 0;
            for (int s = j; s < SS; s += 64) lm = max(lm, hidx[b * SS + s]);
            ired[j] = lm;
        }
        barr128();
        if (tid == 0) {
            int m = 0;
            for (int i = 0; i < 64; i++) m = max(m, ired[i]);
            sh_xlen = m;
        }
        barr128();
    }
    const int xlen = sh_xlen;
    const int cmax = (xlen - 1) >> 7;
    int sready = 0;

    unsigned char* bp = u.s.bp;
    float Tcolh[18];
    float TjS = 0.f;
    const int ibase = h * 18;
    if (j < NT) {
#pragma unroll
        for (int i = 0; i < 18; i++) Tcolh[i] = trans[(ibase + i) * NT + j];
        TjS = trans[j * NT + TSTOP];
    }

    if (tid == 0) { wait_flag(b * 4 + 0); sready = 1; __threadfence(); }
    barr128();

    if (h == 0 && j < NT)
        buf[0][j] = g_emit[(b * SS) * NT + j] + trans[TSTART * NT + j];
    barr128();

    const float* em = g_emit + (long long)b * SS * NT;
    float emnext = (xlen > 1 && h == 0 && j < NT) ? em[NT + j] : 0.f;
    int t = 1;
    for (int c = 0; c <= cmax; c++) {
        const int wc = min(c + 1, cmax);
        if (tid == 0) {
            for (; sready <= wc; sready++) wait_flag(b * 4 + sready);
            __threadfence();
        }
        barr128();
        const int tend = min((c + 1) * CHUNK, xlen);
        for (; t < tend; t++) {
            const int cur = t & 1, prev = cur ^ 1;
            float ec = emnext;
            if (t + 1 < xlen && h == 0 && j < NT) emnext = em[(t + 1) * NT + j];
            if (j < NT) {
                // best over this half's 18 candidates: 3 chains of 6, first-max
                float bb3[3] = {-1e30f, -1e30f, -1e30f};
                int   bi3[3] = {ibase, ibase + 6, ibase + 12};
#pragma unroll
                for (int c3 = 0; c3 < 3; c3++) {
#pragma unroll
                    for (int k = 0; k < 6; k++) {
                        int il = c3 * 6 + k;
                        float v = buf[prev][ibase + il] + Tcolh[il];
                        bool gt = v > bb3[c3];
                        bb3[c3] = gt ? v : bb3[c3];
                        bi3[c3] = gt ? (ibase + il) : bi3[c3];
                    }
                }
                float best = bb3[0]; int bi = bi3[0];
                if (bb3[1] > best) { best = bb3[1]; bi = bi3[1]; }
                if (bb3[2] > best) { best = bb3[2]; bi = bi3[2]; }
                candv[h][j] = best;
                candi[h][j] = bi;
            }
            barr128();
            if (h == 0 && j < NT) {
                float v0 = candv[0][j], v1 = candv[1][j];
                // tie -> h=0 (lower indices), matching first-argmax
                bool g1 = v1 > v0;
                float best = g1 ? v1 : v0;
                int bi = g1 ? candi[1][j] : candi[0][j];
                buf[cur][j] = best + ec;
                bp[(t - 1) * NT + j] = (unsigned char)bi;
            }
            barr128();
        }
    }
    const int lastbuf = (xlen >= 2) ? ((xlen - 1) & 1) : 0;
    if (h == 0 && j < NT) red[j] = buf[lastbuf][j] + TjS;
    barr128();
    if (tid == 0) {
        float bs = -1e30f; int lt = 0;
        for (int i = 0; i < NT; i++) {
            float v = red[i];
            if (v > bs) { bs = v; lt = i; }
        }
        out[1 + BB * SS + b] = bs;
        sh_last = lt;
    }
    barr128();

    float* op = out + 1 + b * SS;
    for (int s = xlen + tid; s < SS; s += 128) op[s] = 0.f;
    if (tid == 0 && xlen > 0) {
        int tag = sh_last;
        op[xlen - 1] = (float)tag;
        for (int t2 = xlen - 1; t2 >= 1; t2--) {
            tag = bp[(t2 - 1) * NT + tag];
            op[t2 - 1] = (float)tag;
        }
    }
}

extern "C" void kernel_launch(void* const* d_in, const int* in_sizes, int n_in,
                              void* d_out, int out_size) {
    const float* x1    = (const float*)d_in[0];
    const int*   hidx  = (const int*)  d_in[1];
    const int*   tags  = (const int*)  d_in[2];
    const float* W     = (const float*)d_in[3];
    const float* bias  = (const float*)d_in[4];
    const float* trans = (const float*)d_in[5];
    float* out = (float*)d_out;

    init_kernel<<<1, 256>>>();
    fused_kernel<<<SCAN_BLOCKS + GEMM_BLOCKS + 1, 288>>>(
        x1, hidx, W, bias, tags, trans, out);
}

// round 17
// speedup vs baseline: 1.5475x; 1.1875x over previous
#include <cuda_runtime.h>
#include <math.h>

#define BB 64
#define SS 512
#define HH 768
#define NT 36
#define TSTART 34
#define TSTOP 35
#define SCAN_BLOCKS 128    // 64 NLL + 64 Viterbi
#define GEMM_BLOCKS 256    // 128 rows per block, col-split: 9 warps x 4 cols
#define CHUNK 128          // rows per readiness chunk (4 per batch)
#define KT 16              // k-tile
#define NTILES (HH / KT)   // 48

// Scratch (device globals — no allocation allowed)
__device__ float g_emit [BB * SS * NT];
__device__ float g_eemit[BB * SS * NT];
__device__ float g_lossb[BB];
__device__ int   g_done [BB * 4];
__device__ int   g_nllcnt;

// ---------------- helpers ----------------
__device__ __forceinline__ unsigned long long pack2(float a, float b) {
    unsigned long long r;
    asm("mov.b64 %0, {%1, %2};" : "=l"(r) : "f"(a), "f"(b));
    return r;
}
__device__ __forceinline__ void unpack2(unsigned long long v, float& a, float& b) {
    asm("mov.b64 {%0, %1}, %2;" : "=f"(a), "=f"(b) : "l"(v));
}
__device__ __forceinline__ unsigned long long fma2(unsigned long long a,
                                                   unsigned long long b,
                                                   unsigned long long c) {
    unsigned long long d;
    asm("fma.rn.f32x2 %0, %1, %2, %3;" : "=l"(d) : "l"(a), "l"(b), "l"(c));
    return d;
}
__device__ __forceinline__ unsigned long long add2(unsigned long long a,
                                                   unsigned long long b) {
    unsigned long long d;
    asm("add.rn.f32x2 %0, %1, %2;" : "=l"(d) : "l"(a), "l"(b));
    return d;
}
__device__ __forceinline__ void barr64() {
    asm volatile("bar.sync 0, 64;" ::: "memory");
}
__device__ __forceinline__ void wait_flag(int idx) {
    volatile int* f = &g_done[idx];
    while (*f == 0) __nanosleep(64);
}
__device__ __forceinline__ void cp16(unsigned int smem_dst, const void* gsrc) {
    asm volatile("cp.async.cg.shared.global [%0], [%1], 16;"
                 :: "r"(smem_dst), "l"(gsrc));
}
__device__ __forceinline__ void cp_commit() {
    asm volatile("cp.async.commit_group;" ::: "memory");
}
template<int N>
__device__ __forceinline__ void cp_wait() {
    asm volatile("cp.async.wait_group %0;" :: "n"(N) : "memory");
}

// ---------------- init ----------------
__global__ void init_kernel() {
    int i = threadIdx.x + blockIdx.x * blockDim.x;
    if (i < BB * 4) g_done[i] = 0;
    if (i == 0) g_nllcnt = 0;
}

union SmemU {
    struct {                          // 25088 B GEMM tiles (double-buffered)
        float Xs[2][128][20];
        float Ws[2][KT][36];
    } g;
    struct {                          // 23616 B NLL state
        float eeb[2][64][36];         // staged exp(emit) sub-chunks
        float Tsh[NT * NT];
    } s;
    struct {                          // 36828 B Viterbi state
        float emb[2][64][36];         // staged emit sub-chunks
        unsigned char bp[(SS - 1) * NT];
    } v;
};

// ---------------- fused kernel ----------------
// blocks [0,64):    NLL scan (batch bid), threads 0-63
// blocks [64,128):  Viterbi (batch bid-64), threads 0-63
// blocks [128,384): GEMM, chunk-major: c=(bid-128)>>6, b=(bid-128)&63, 128 rows
// block  384:       loss reducer
__global__ __launch_bounds__(288, 3) void fused_kernel(
    const float* __restrict__ x1, const int* __restrict__ hidx,
    const float* __restrict__ W, const float* __restrict__ bias,
    const int* __restrict__ tags, const float* __restrict__ trans,
    float* __restrict__ out)
{
    __shared__ __align__(16) SmemU u;
    __shared__ int   src[128];
    __shared__ __align__(16) float buf[2][NT];
    __shared__ float red[64];
    __shared__ int   ired[64];
    __shared__ int   sh_xlen, sh_last;

    const int tid = threadIdx.x;
    const int bid = blockIdx.x;

    if (bid >= SCAN_BLOCKS && bid < SCAN_BLOCKS + GEMM_BLOCKS) {
        // ================= GEMM (unchanged, near floor) =====================
        const int gb = bid - SCAN_BLOCKS;
        const int c  = gb >> 6;
        const int b  = gb & 63;
        const int rowbase = b * SS + c * CHUNK;
        const int warp = tid >> 5;
        const int lane = tid & 31;
        const int cw   = warp * 4;

        if (tid < 128) {
            int g = rowbase + tid;
            src[tid] = (b << 9) * HH + hidx[g] * HH;
        }
        __syncthreads();

        const unsigned int sX =
            (unsigned int)__cvta_generic_to_shared(&u.g.Xs[0][0][0]);
        const unsigned int sW =
            (unsigned int)__cvta_generic_to_shared(&u.g.Ws[0][0][0]);

        unsigned long long acc[4][2];
#pragma unroll
        for (int r4 = 0; r4 < 4; r4++) { acc[r4][0] = 0ull; acc[r4][1] = 0ull; }

        auto stage = [&](int kt, int bsel) {
            const int k0 = kt * KT;
            for (int i = tid; i < 512; i += 288) {
                int row = i >> 2, c4 = i & 3;
                const char* gp =
                    reinterpret_cast<const char*>(x1 + src[row] + k0) + c4 * 16;
                cp16(sX + (bsel * 128 * 20 + row * 20 + c4 * 4) * 4, gp);
            }
            if (tid < 144) {
                const char* gp =
                    reinterpret_cast<const char*>(W + k0 * 36) + tid * 16;
                cp16(sW + bsel * KT * 36 * 4 + tid * 16, gp);
            }
            cp_commit();
        };

        stage(0, 0);
        for (int kt = 0; kt < NTILES; kt++) {
            const int bsel = kt & 1;
            if (kt + 1 < NTILES) { stage(kt + 1, bsel ^ 1); cp_wait<1>(); }
            else                 { cp_wait<0>(); }
            __syncthreads();

            const float* Xb = &u.g.Xs[bsel][0][0];
            const float* Wb = &u.g.Ws[bsel][0][0];
#pragma unroll
            for (int g = 0; g < 4; g++) {
                float4 xv0 = *reinterpret_cast<const float4*>(Xb + (lane)      * 20 + g * 4);
                float4 xv1 = *reinterpret_cast<const float4*>(Xb + (lane + 32) * 20 + g * 4);
                float4 xv2 = *reinterpret_cast<const float4*>(Xb + (lane + 64) * 20 + g * 4);
                float4 xv3 = *reinterpret_cast<const float4*>(Xb + (lane + 96) * 20 + g * 4);
#pragma unroll
                for (int kk = 0; kk < 4; kk++) {
                    ulonglong2 wv = *reinterpret_cast<const ulonglong2*>(
                        Wb + (g * 4 + kk) * 36 + cw);
                    float x0 = (kk == 0) ? xv0.x : (kk == 1) ? xv0.y : (kk == 2) ? xv0.z : xv0.w;
                    float x1v = (kk == 0) ? xv1.x : (kk == 1) ? xv1.y : (kk == 2) ? xv1.z : xv1.w;
                    float x2 = (kk == 0) ? xv2.x : (kk == 1) ? xv2.y : (kk == 2) ? xv2.z : xv2.w;
                    float x3 = (kk == 0) ? xv3.x : (kk == 1) ? xv3.y : (kk == 2) ? xv3.z : xv3.w;
                    unsigned long long p0 = pack2(x0, x0);
                    unsigned long long p1 = pack2(x1v, x1v);
                    unsigned long long p2 = pack2(x2, x2);
                    unsigned long long p3 = pack2(x3, x3);
                    acc[0][0] = fma2(p0, wv.x, acc[0][0]);
                    acc[0][1] = fma2(p0, wv.y, acc[0][1]);
                    acc[1][0] = fma2(p1, wv.x, acc[1][0]);
                    acc[1][1] = fma2(p1, wv.y, acc[1][1]);
                    acc[2][0] = fma2(p2, wv.x, acc[2][0]);
                    acc[2][1] = fma2(p2, wv.y, acc[2][1]);
                    acc[3][0] = fma2(p3, wv.x, acc[3][0]);
                    acc[3][1] = fma2(p3, wv.y, acc[3][1]);
                }
            }
            __syncthreads();
        }

        const float b0 = bias[cw], b1 = bias[cw + 1], b2 = bias[cw + 2], b3 = bias[cw + 3];
#pragma unroll
        for (int r4 = 0; r4 < 4; r4++) {
            const int row = lane + 32 * r4;
            const long long grow = rowbase + row;
            float v0, v1, v2, v3;
            unpack2(acc[r4][0], v0, v1);
            unpack2(acc[r4][1], v2, v3);
            v0 += b0; v1 += b1; v2 += b2; v3 += b3;
            v0 = (v0 >= 0.f) ? v0 : 0.01f * v0;
            v1 = (v1 >= 0.f) ? v1 : 0.01f * v1;
            v2 = (v2 >= 0.f) ? v2 : 0.01f * v2;
            v3 = (v3 >= 0.f) ? v3 : 0.01f * v3;
            *reinterpret_cast<float4*>(g_emit + grow * 36 + cw) =
                make_float4(v0, v1, v2, v3);
            *reinterpret_cast<float4*>(g_eemit + grow * 36 + cw) =
                make_float4(__expf(v0), __expf(v1), __expf(v2), __expf(v3));
        }
        __syncthreads();
        if (tid == 0) {
            __threadfence();
            atomicExch(&g_done[b * 4 + c], 1);
        }
        return;
    }

    if (bid >= SCAN_BLOCKS + GEMM_BLOCKS) {
        // ================= loss reducer =================
        if (tid == 0) {
            volatile int* c = &g_nllcnt;
            while (*c < BB) __nanosleep(256);
            __threadfence();
            float a = 0.f;
            for (int i = 0; i < BB; i++) a += g_lossb[i];
            out[0] = a;
        }
        return;
    }

    // ================= SCANS (threads 0-63 only) =================
    if (tid >= 64) return;

    const int b = bid & 63;
    const bool viterbi = (bid >= BB);
    const int j = tid;

    // xlen = max(head_indexes[b, :])
    {
        int lm = 0;
        for (int s = tid; s < SS; s += 64) lm = max(lm, hidx[b * SS + s]);
        ired[tid] = lm;
        barr64();
        if (tid == 0) {
            int m = 0;
            for (int i = 0; i < 64; i++) m = max(m, ired[i]);
            sh_xlen = m;
        }
        barr64();
    }
    const int xlen = sh_xlen;
    const int smax = (xlen - 1) >> 6;   // 64-step sub-chunks

    if (!viterbi) {
        // ---------------- NLL ----------------
        float* Tsh = u.s.Tsh;
        for (int i = tid; i < NT * NT; i += 64) Tsh[i] = trans[i];
        barr64();

        unsigned long long Ecol2[18];
        float Cl = 0.f;
        if (j < NT) {
#pragma unroll
            for (int p = 0; p < 18; p++)
                Ecol2[p] = pack2(__expf(Tsh[(2 * p) * NT + j]),
                                 __expf(Tsh[(2 * p + 1) * NT + j]));
        }

        const unsigned int sE =
            (unsigned int)__cvta_generic_to_shared(&u.s.eeb[0][0][0]);
        const float* eeG = g_eemit + (long long)b * SS * NT;
        auto stage_e = [&](int s) {
            const char* gp = reinterpret_cast<const char*>(eeG + (s << 6) * NT);
            const unsigned int dst = sE + (s & 1) * 9216;
            for (int i = tid; i < 576; i += 64) cp16(dst + i * 16, gp + i * 16);
            cp_commit();
        };

        if (tid == 0) { wait_flag(b * 4 + 0); __threadfence(); }
        barr64();
        if (j < NT)
            buf[0][j] = __expf(g_emit[(b * SS) * NT + j] + Tsh[TSTART * NT + j]);
        stage_e(0);                      // rows 0-63, flag 0 held
        barr64();

        int t = 1;
        for (int s = 0; s <= smax; s++) {
            // lookahead 1: stage s+1 into buffer (s+1)&1 (disjoint from read buf)
            if (s + 1 <= smax) {
                const int need = (s + 1) >> 1;   // 128-row flag for sub-chunk s+1
                if (need > 0) {
                    if (tid == 0) { wait_flag(b * 4 + need); __threadfence(); }
                    barr64();
                }
                stage_e(s + 1);
                cp_wait<1>();                    // retire group s
            } else {
                cp_wait<0>();
            }
            barr64();

            const float* eb = &u.s.eeb[s & 1][0][0];
            const int tend = min((s + 1) * 64, xlen);
            for (; t < tend; t++) {
                const int cur = t & 1, prev = cur ^ 1;
                if (j < NT) {
                    const unsigned long long* vp =
                        reinterpret_cast<const unsigned long long*>(&buf[prev][0]);
                    float nb = buf[prev][0];
                    float rinv = 1.0f / nb;
                    float eecur = eb[(t & 63) * NT + j];
                    unsigned long long c0 = 0, c1 = 0, c2 = 0, c3 = 0;
#pragma unroll
                    for (int p = 0; p < 16; p += 4) {
                        c0 = fma2(vp[p],     Ecol2[p],     c0);
                        c1 = fma2(vp[p + 1], Ecol2[p + 1], c1);
                        c2 = fma2(vp[p + 2], Ecol2[p + 2], c2);
                        c3 = fma2(vp[p + 3], Ecol2[p + 3], c3);
                    }
                    c0 = fma2(vp[16], Ecol2[16], c0);
                    c1 = fma2(vp[17], Ecol2[17], c1);
                    unsigned long long cs = add2(add2(c0, c1), add2(c2, c3));
                    float sa, sbv; unpack2(cs, sa, sbv);
                    buf[cur][j] = (sa + sbv) * rinv * eecur;
                    Cl += __logf(nb);
                }
                barr64();
            }
        }
        const int lastbuf = (xlen >= 2) ? ((xlen - 1) & 1) : 0;
        if (j < NT) red[j] = buf[lastbuf][j] * __expf(Tsh[j * NT + TSTOP]);
        barr64();

        float logZ = 0.f;
        if (tid == 0) {
            float sZ = 0.f;
            for (int i = 0; i < NT; i++) sZ += red[i];
            logZ = Cl + __logf(sZ);
        }
        barr64();

        const int* tg = tags + b * SS;
        {
            float gp = 0.f;
            for (int s = tid; s < xlen; s += 64) {
                int cs = tg[s];
                gp += g_emit[((long long)b * SS + s) * NT + cs];
                if (s >= 1) gp += Tsh[tg[s - 1] * NT + cs];
            }
            red[tid] = gp;
        }
        barr64();
        if (tid == 0) {
            float g = 0.f;
            for (int i = 0; i < 64; i++) g += red[i];
            int li = (xlen > 0) ? (xlen - 1) : 0;
            g += Tsh[TSTART * NT + tg[0]] + Tsh[tg[li] * NT + TSTOP];
            g_lossb[b] = logZ - g;
            __threadfence();
            atomicAdd(&g_nllcnt, 1);
        }
    } else {
        // ---------------- Viterbi ----------------
        unsigned char* bp = u.v.bp;
        float Tcol[NT];
        float TjS = 0.f;
        if (j < NT) {
#pragma unroll
            for (int i = 0; i < NT; i++) Tcol[i] = trans[i * NT + j];
            TjS = trans[j * NT + TSTOP];
        }

        const unsigned int sE =
            (unsigned int)__cvta_generic_to_shared(&u.v.emb[0][0][0]);
        const float* emG = g_emit + (long long)b * SS * NT;
        auto stage_e = [&](int s) {
            const char* gp = reinterpret_cast<const char*>(emG + (s << 6) * NT);
            const unsigned int dst = sE + (s & 1) * 9216;
            for (int i = tid; i < 576; i += 64) cp16(dst + i * 16, gp + i * 16);
            cp_commit();
        };

        if (tid == 0) { wait_flag(b * 4 + 0); __threadfence(); }
        barr64();
        if (j < NT)
            buf[0][j] = g_emit[(b * SS) * NT + j] + trans[TSTART * NT + j];
        stage_e(0);
        barr64();

        int t = 1;
        for (int s = 0; s <= smax; s++) {
            if (s + 1 <= smax) {
                const int need = (s + 1) >> 1;
                if (need > 0) {
                    if (tid == 0) { wait_flag(b * 4 + need); __threadfence(); }
                    barr64();
                }
                stage_e(s + 1);
                cp_wait<1>();
            } else {
                cp_wait<0>();
            }
            barr64();

            const float* eb = &u.v.emb[s & 1][0][0];
            const int tend = min((s + 1) * 64, xlen);
            for (; t < tend; t++) {
                const int cur = t & 1, prev = cur ^ 1;
                if (j < NT) {
                    float ec = eb[(t & 63) * NT + j];
                    // 6 chains of 6 contiguous candidates, first-max preserved
                    float bb6[6];
                    int   bi6[6];
#pragma unroll
                    for (int c6 = 0; c6 < 6; c6++) {
                        bb6[c6] = -1e30f; bi6[c6] = c6 * 6;
#pragma unroll
                        for (int k = 0; k < 6; k++) {
                            int i = c6 * 6 + k;
                            float v = buf[prev][i] + Tcol[i];
                            bool gt = v > bb6[c6];
                            bb6[c6] = gt ? v : bb6[c6];
                            bi6[c6] = gt ? i : bi6[c6];
                        }
                    }
                    float best = bb6[0]; int bi = bi6[0];
#pragma unroll
                    for (int c6 = 1; c6 < 6; c6++)
                        if (bb6[c6] > best) { best = bb6[c6]; bi = bi6[c6]; }
                    buf[cur][j] = best + ec;
                    bp[(t - 1) * NT + j] = (unsigned char)bi;
                }
                barr64();
            }
        }
        const int lastbuf = (xlen >= 2) ? ((xlen - 1) & 1) : 0;
        if (j < NT) red[j] = buf[lastbuf][j] + TjS;
        barr64();
        if (tid == 0) {
            float bs = -1e30f; int lt = 0;
            for (int i = 0; i < NT; i++) {
                float v = red[i];
                if (v > bs) { bs = v; lt = i; }
            }
            out[1 + BB * SS + b] = bs;
            sh_last = lt;
        }
        barr64();

        float* op = out + 1 + b * SS;
        for (int s = xlen + tid; s < SS; s += 64) op[s] = 0.f;
        if (tid == 0 && xlen > 0) {
            int tag = sh_last;
            op[xlen - 1] = (float)tag;
            for (int t2 = xlen - 1; t2 >= 1; t2--) {
                tag = bp[(t2 - 1) * NT + tag];
                op[t2 - 1] = (float)tag;
            }
        }
    }
}

extern "C" void kernel_launch(void* const* d_in, const int* in_sizes, int n_in,
                              void* d_out, int out_size) {
    const float* x1    = (const float*)d_in[0];
    const int*   hidx  = (const int*)  d_in[1];
    const int*   tags  = (const int*)  d_in[2];
    const float* W     = (const float*)d_in[3];
    const float* bias  = (const float*)d_in[4];
    const float* trans = (const float*)d_in[5];
    float* out = (float*)d_out;

    init_kernel<<<1, 256>>>();
    fused_kernel<<<SCAN_BLOCKS + GEMM_BLOCKS + 1, 288>>>(
        x1, hidx, W, bias, tags, trans, out);
}